// round 10
// baseline (speedup 1.0000x reference)
#include <cuda_runtime.h>
#include <cuda_fp16.h>
#include <cstdint>
#include <cstddef>

#define NT 512
#define XP 72   // halves per smem matrix row (144B: conflict-free ldmatrix, 16B-aligned)

namespace {
constexpr int Bb = 2, Ss = 512, Ll = 384, CMc = 64;

struct __align__(16) SMem {
    __half x[512 * XP];     // post-LN x fp16, row-major [s][c]      73,728B
    __half vt[512 * XP];    // v, then t                              73,728B
    __half wvg[128 * XP];   // B rows n: n<64 -> wv col n, else wg col n-64; cols k
    __half wot[64 * XP];    // B rows n: wo col n
    float LG[8 * 512];      // logits -> attn [h][s]
    float maskS[512];
    float pbuf[16 * 64];    // LN-fold qin partials; og partials
    __half a_h[8 * XP];     // a fp16 [h][j] (logits B tile)
    float qin[64];
    float qsm[64];
    float og[64];
    float red[16];
};
}  // namespace

__device__ __forceinline__ uint32_t s2u(const void* p) {
    uint32_t a;
    asm("{ .reg .u64 t; cvta.to.shared.u64 t, %1; cvt.u32.u64 %0, t; }" : "=r"(a) : "l"(p));
    return a;
}
__device__ __forceinline__ void ldmA(uint32_t* a, uint32_t addr) {
    asm volatile("ldmatrix.sync.aligned.m8n8.x4.shared.b16 {%0,%1,%2,%3}, [%4];"
                 : "=r"(a[0]), "=r"(a[1]), "=r"(a[2]), "=r"(a[3]) : "r"(addr));
}
__device__ __forceinline__ void mma16816(float* d, const uint32_t* a, const uint32_t* b) {
    asm volatile(
        "mma.sync.aligned.m16n8k16.row.col.f32.f16.f16.f32 "
        "{%0,%1,%2,%3}, {%4,%5,%6,%7}, {%8,%9}, {%0,%1,%2,%3};"
        : "+f"(d[0]), "+f"(d[1]), "+f"(d[2]), "+f"(d[3])
        : "r"(a[0]), "r"(a[1]), "r"(a[2]), "r"(a[3]), "r"(b[0]), "r"(b[1]));
}
__device__ __forceinline__ float sgm(float x) { return 1.0f / (1.0f + __expf(-x)); }

__global__ void __launch_bounds__(NT, 1)
msa_col_global_attn(const float* __restrict__ m, const float* __restrict__ msa_mask,
                    const float* __restrict__ lnw, const float* __restrict__ lnb,
                    const float* __restrict__ wq, const float* __restrict__ wk,
                    const float* __restrict__ wv, const float* __restrict__ wg,
                    const float* __restrict__ bg, const float* __restrict__ wo,
                    const float* __restrict__ bo, float* __restrict__ out)
{
    extern __shared__ __align__(16) char smraw[];
    SMem& sm = *reinterpret_cast<SMem*>(smraw);
    const int tid = threadIdx.x;
    const int w = tid >> 5, lane = tid & 31;
    const int mw = w >> 2, nw = w & 3;   // warp tile coords for GEMM passes
    const int b = blockIdx.x / Ll, l = blockIdx.x - b * Ll;
    const size_t rowStride = (size_t)Ll * CMc;
    const float* mBase = m + ((size_t)b * Ss * Ll + l) * CMc;
    float* oBase = out + ((size_t)b * Ss * Ll + l) * CMc;

    // ---- Phase 0: mask + weights + LayerNorm (8 cols/thread) + folded qin sum ----
    float mk = msa_mask[((size_t)b * Ss + tid) * Ll + l];
    sm.maskS[tid] = mk;
    {
        float ms = mk;
#pragma unroll
        for (int o = 16; o; o >>= 1) ms += __shfl_xor_sync(0xffffffffu, ms, o);
        if (lane == 0) sm.red[w] = ms;
    }
    for (int idx = tid; idx < 8192; idx += NT) {
        int n = idx & 127, k = idx >> 7;
        float v = (n < 64) ? __ldg(&wv[k * 64 + n]) : __ldg(&wg[k * 64 + (n - 64)]);
        sm.wvg[n * XP + k] = __float2half(v);
    }
    for (int idx = tid; idx < 4096; idx += NT) {
        int n = idx & 63, k = idx >> 6;
        sm.wot[n * XP + k] = __float2half(__ldg(&wo[k * 64 + n]));
    }
    {
        const int gi = lane >> 3;        // row within quad
        const int ci = (lane & 7) * 8;   // col base (8 cols per thread)
        const float4 lw0 = *reinterpret_cast<const float4*>(&lnw[ci]);
        const float4 lw1 = *reinterpret_cast<const float4*>(&lnw[ci + 4]);
        const float4 lb0 = *reinterpret_cast<const float4*>(&lnb[ci]);
        const float4 lb1 = *reinterpret_cast<const float4*>(&lnb[ci + 4]);
        float qac[8] = {0, 0, 0, 0, 0, 0, 0, 0};
        const float* p0 = mBase + (size_t)(w * 32 + gi) * rowStride + ci;
        float4 va = *reinterpret_cast<const float4*>(p0);
        float4 vb = *reinterpret_cast<const float4*>(p0 + 4);
#pragma unroll 1
        for (int q8 = 0; q8 < 8; q8++) {
            float4 na, nb;
            if (q8 < 7) {
                const float* pn = mBase + (size_t)(w * 32 + (q8 + 1) * 4 + gi) * rowStride + ci;
                na = *reinterpret_cast<const float4*>(pn);
                nb = *reinterpret_cast<const float4*>(pn + 4);
            }
            int s = w * 32 + q8 * 4 + gi;
            float su = (va.x + va.y) + (va.z + va.w) + (vb.x + vb.y) + (vb.z + vb.w);
            float sq = va.x * va.x;
            sq = fmaf(va.y, va.y, sq); sq = fmaf(va.z, va.z, sq); sq = fmaf(va.w, va.w, sq);
            sq = fmaf(vb.x, vb.x, sq); sq = fmaf(vb.y, vb.y, sq);
            sq = fmaf(vb.z, vb.z, sq); sq = fmaf(vb.w, vb.w, sq);
#pragma unroll
            for (int o = 4; o; o >>= 1) {
                su += __shfl_xor_sync(0xffffffffu, su, o);
                sq += __shfl_xor_sync(0xffffffffu, sq, o);
            }
            float mu = su * (1.0f / 64.0f);
            float var = sq * (1.0f / 64.0f) - mu * mu;
            float rs = rsqrtf(var + 1e-5f);
            float v0 = (va.x - mu) * rs * lw0.x + lb0.x;
            float v1 = (va.y - mu) * rs * lw0.y + lb0.y;
            float v2 = (va.z - mu) * rs * lw0.z + lb0.z;
            float v3 = (va.w - mu) * rs * lw0.w + lb0.w;
            float v4 = (vb.x - mu) * rs * lw1.x + lb1.x;
            float v5 = (vb.y - mu) * rs * lw1.y + lb1.y;
            float v6 = (vb.z - mu) * rs * lw1.z + lb1.z;
            float v7 = (vb.w - mu) * rs * lw1.w + lb1.w;
            __half2 h01 = __floats2half2_rn(v0, v1);
            __half2 h23 = __floats2half2_rn(v2, v3);
            __half2 h45 = __floats2half2_rn(v4, v5);
            __half2 h67 = __floats2half2_rn(v6, v7);
            uint4 pk;
            pk.x = *reinterpret_cast<uint32_t*>(&h01);
            pk.y = *reinterpret_cast<uint32_t*>(&h23);
            pk.z = *reinterpret_cast<uint32_t*>(&h45);
            pk.w = *reinterpret_cast<uint32_t*>(&h67);
            *reinterpret_cast<uint4*>(&sm.x[s * XP + ci]) = pk;
            float mm = __shfl_sync(0xffffffffu, mk, q8 * 4 + gi);
            qac[0] = fmaf(v0, mm, qac[0]); qac[1] = fmaf(v1, mm, qac[1]);
            qac[2] = fmaf(v2, mm, qac[2]); qac[3] = fmaf(v3, mm, qac[3]);
            qac[4] = fmaf(v4, mm, qac[4]); qac[5] = fmaf(v5, mm, qac[5]);
            qac[6] = fmaf(v6, mm, qac[6]); qac[7] = fmaf(v7, mm, qac[7]);
            va = na; vb = nb;
        }
#pragma unroll
        for (int k = 0; k < 8; k++) {
            qac[k] += __shfl_xor_sync(0xffffffffu, qac[k], 8);
            qac[k] += __shfl_xor_sync(0xffffffffu, qac[k], 16);
        }
        if (lane < 8) {
            *reinterpret_cast<float4*>(&sm.pbuf[w * 64 + ci]) =
                make_float4(qac[0], qac[1], qac[2], qac[3]);
            *reinterpret_cast<float4*>(&sm.pbuf[w * 64 + ci + 4]) =
                make_float4(qac[4], qac[5], qac[6], qac[7]);
        }
    }
    __syncthreads();  // S1: x, weights, mask, qin partials ready

    // ---- warp-0 chain: qin -> q -> a_h (fp16, [h][j]) ----
    if (w == 0) {
        float d = 0.f;
#pragma unroll
        for (int i = 0; i < 16; i++) d += sm.red[i];
        float inv = 1.0f / fmaxf(d, 1.0f);
        float q0 = 0.f, q1 = 0.f;
#pragma unroll
        for (int i = 0; i < 16; i++) {
            q0 += sm.pbuf[i * 64 + lane];
            q1 += sm.pbuf[i * 64 + lane + 32];
        }
        sm.qin[lane] = q0 * inv;
        sm.qin[lane + 32] = q1 * inv;
        __syncwarp();
        float a0 = 0.f, a1 = 0.f;
#pragma unroll
        for (int j = 0; j < 64; j++) {
            float qj = sm.qin[j];
            a0 = fmaf(qj, __ldg(&wq[j * 64 + lane]), a0);
            a1 = fmaf(qj, __ldg(&wq[j * 64 + lane + 32]), a1);
        }
        sm.qsm[lane] = a0;
        sm.qsm[lane + 32] = a1;
        __syncwarp();
#pragma unroll 1
        for (int t = 0; t < 16; t++) {
            int idx = t * 32 + lane;
            int j = idx >> 3, h = idx & 7;
            float acc = 0.f;
#pragma unroll
            for (int c = 0; c < 8; c++)
                acc = fmaf(sm.qsm[h * 8 + c], __ldg(&wk[j * 64 + h * 8 + c]), acc);
            sm.a_h[h * XP + j] = __float2half(acc * 0.35355339059327373f);  // 1/sqrt(C)
        }
    }
    __syncthreads();  // S2: a_h ready

    // ---- Logits via HMMA: logits[s,h] = x[s,:] @ a[:,h], masked -> LG fp32 ----
    {
        uint32_t Bf[4][2];
#pragma unroll
        for (int kt = 0; kt < 4; kt++) {
            int row = lane >> 2;                    // h (n index)
            int col = kt * 16 + (lane & 3) * 2;     // j (k index)
            Bf[kt][0] = *reinterpret_cast<const uint32_t*>(&sm.a_h[row * XP + col]);
            Bf[kt][1] = *reinterpret_cast<const uint32_t*>(&sm.a_h[row * XP + col + 8]);
        }
#pragma unroll
        for (int mt = 0; mt < 2; mt++) {
            int s0 = w * 32 + mt * 16;
            uint32_t A[4][4];
#pragma unroll
            for (int kt = 0; kt < 4; kt++)
                ldmA(A[kt], s2u(&sm.x[(s0 + (lane & 15)) * XP + kt * 16 + ((lane >> 4) << 3)]));
            float acc[4] = {0, 0, 0, 0};
#pragma unroll
            for (int kt = 0; kt < 4; kt++) mma16816(acc, A[kt], Bf[kt]);
            int r = s0 + (lane >> 2);
            int h0 = (lane & 3) * 2;
            float mkA = sm.maskS[r], mkB = sm.maskS[r + 8];
            sm.LG[h0 * 512 + r]             = (mkA != 0.0f) ? acc[0] : -1e9f;
            sm.LG[(h0 + 1) * 512 + r]       = (mkA != 0.0f) ? acc[1] : -1e9f;
            sm.LG[h0 * 512 + r + 8]         = (mkB != 0.0f) ? acc[2] : -1e9f;
            sm.LG[(h0 + 1) * 512 + r + 8]   = (mkB != 0.0f) ? acc[3] : -1e9f;
        }
    }
    __syncthreads();  // S3: logits ready

    // ---- softmax, warp w<8 owns head w ----
    if (w < 8) {
        float vals[16];
        float lm = -3.4e38f;
#pragma unroll
        for (int k = 0; k < 16; k++) {
            vals[k] = sm.LG[w * 512 + lane + k * 32];
            lm = fmaxf(lm, vals[k]);
        }
#pragma unroll
        for (int o = 16; o; o >>= 1) lm = fmaxf(lm, __shfl_xor_sync(0xffffffffu, lm, o));
        float ls = 0.f;
#pragma unroll
        for (int k = 0; k < 16; k++) {
            vals[k] = __expf(vals[k] - lm);
            ls += vals[k];
        }
#pragma unroll
        for (int o = 16; o; o >>= 1) ls += __shfl_xor_sync(0xffffffffu, ls, o);
        float inv = 1.0f / ls;
#pragma unroll
        for (int k = 0; k < 16; k++) sm.LG[w * 512 + lane + k * 32] = vals[k] * inv;
    }
    __syncthreads();  // S4: attn ready

    // ---- Pass V: v = x @ wv  (warp: 128 rows x 16 cols) -> vt fp16 ----
    {
        uint32_t B[2][4][2];
#pragma unroll
        for (int nt = 0; nt < 2; nt++)
#pragma unroll
            for (int kt = 0; kt < 4; kt++) {
                int row = nw * 16 + nt * 8 + (lane >> 2);
                int col = kt * 16 + (lane & 3) * 2;
                B[nt][kt][0] = *reinterpret_cast<const uint32_t*>(&sm.wvg[row * XP + col]);
                B[nt][kt][1] = *reinterpret_cast<const uint32_t*>(&sm.wvg[row * XP + col + 8]);
            }
#pragma unroll 1
        for (int mt = 0; mt < 8; mt++) {
            int s0 = mw * 128 + mt * 16;
            uint32_t A[4][4];
#pragma unroll
            for (int kt = 0; kt < 4; kt++)
                ldmA(A[kt], s2u(&sm.x[(s0 + (lane & 15)) * XP + kt * 16 + ((lane >> 4) << 3)]));
            float acc[2][4] = {{0, 0, 0, 0}, {0, 0, 0, 0}};
#pragma unroll
            for (int kt = 0; kt < 4; kt++)
#pragma unroll
                for (int nt = 0; nt < 2; nt++) mma16816(acc[nt], A[kt], B[nt][kt]);
            int r = s0 + (lane >> 2), c = nw * 16 + (lane & 3) * 2;
#pragma unroll
            for (int nt = 0; nt < 2; nt++) {
                *reinterpret_cast<__half2*>(&sm.vt[r * XP + c + nt * 8]) =
                    __floats2half2_rn(acc[nt][0], acc[nt][1]);
                *reinterpret_cast<__half2*>(&sm.vt[(r + 8) * XP + c + nt * 8]) =
                    __floats2half2_rn(acc[nt][2], acc[nt][3]);
            }
        }
    }
    __syncthreads();  // S5: v ready

    // ---- og[hc] = sum_s attn[hc>>3][s] * v[s][hc] ----
    {
        int hc = tid & 63, ck = tid >> 6;
        const float* ar = &sm.LG[(hc >> 3) * 512 + ck * 64];
        float acc = 0.f;
#pragma unroll 8
        for (int i = 0; i < 64; i++)
            acc = fmaf(ar[i], __half2float(sm.vt[(ck * 64 + i) * XP + hc]), acc);
        sm.pbuf[ck * 64 + hc] = acc;
    }
    __syncthreads();  // S6
    if (tid < 64) {
        float acc = 0.f;
#pragma unroll
        for (int ck = 0; ck < 8; ck++) acc += sm.pbuf[ck * 64 + tid];
        sm.og[tid] = acc;
    }
    __syncthreads();  // S7

    // ---- Pass G: t = og * sigmoid(x @ wg + bg) -> vt (overwrite) ----
    {
        uint32_t B[2][4][2];
#pragma unroll
        for (int nt = 0; nt < 2; nt++)
#pragma unroll
            for (int kt = 0; kt < 4; kt++) {
                int row = 64 + nw * 16 + nt * 8 + (lane >> 2);
                int col = kt * 16 + (lane & 3) * 2;
                B[nt][kt][0] = *reinterpret_cast<const uint32_t*>(&sm.wvg[row * XP + col]);
                B[nt][kt][1] = *reinterpret_cast<const uint32_t*>(&sm.wvg[row * XP + col + 8]);
            }
        int cbase = nw * 16 + (lane & 3) * 2;
        float og0[2], og1[2], bg0[2], bg1[2];
#pragma unroll
        for (int nt = 0; nt < 2; nt++) {
            og0[nt] = sm.og[cbase + nt * 8];
            og1[nt] = sm.og[cbase + nt * 8 + 1];
            bg0[nt] = __ldg(&bg[cbase + nt * 8]);
            bg1[nt] = __ldg(&bg[cbase + nt * 8 + 1]);
        }
#pragma unroll 1
        for (int mt = 0; mt < 8; mt++) {
            int s0 = mw * 128 + mt * 16;
            uint32_t A[4][4];
#pragma unroll
            for (int kt = 0; kt < 4; kt++)
                ldmA(A[kt], s2u(&sm.x[(s0 + (lane & 15)) * XP + kt * 16 + ((lane >> 4) << 3)]));
            float acc[2][4] = {{0, 0, 0, 0}, {0, 0, 0, 0}};
#pragma unroll
            for (int kt = 0; kt < 4; kt++)
#pragma unroll
                for (int nt = 0; nt < 2; nt++) mma16816(acc[nt], A[kt], B[nt][kt]);
            int r = s0 + (lane >> 2);
#pragma unroll
            for (int nt = 0; nt < 2; nt++) {
                float t0 = og0[nt] * sgm(acc[nt][0] + bg0[nt]);
                float t1 = og1[nt] * sgm(acc[nt][1] + bg1[nt]);
                float t2 = og0[nt] * sgm(acc[nt][2] + bg0[nt]);
                float t3 = og1[nt] * sgm(acc[nt][3] + bg1[nt]);
                *reinterpret_cast<__half2*>(&sm.vt[r * XP + cbase + nt * 8]) =
                    __floats2half2_rn(t0, t1);
                *reinterpret_cast<__half2*>(&sm.vt[(r + 8) * XP + cbase + nt * 8]) =
                    __floats2half2_rn(t2, t3);
            }
        }
    }
    __syncthreads();  // S8: t ready

    // ---- Pass O: out = (t @ wo + bo) * mask -> global (direct from D frags) ----
    {
        uint32_t B[2][4][2];
#pragma unroll
        for (int nt = 0; nt < 2; nt++)
#pragma unroll
            for (int kt = 0; kt < 4; kt++) {
                int row = nw * 16 + nt * 8 + (lane >> 2);
                int col = kt * 16 + (lane & 3) * 2;
                B[nt][kt][0] = *reinterpret_cast<const uint32_t*>(&sm.wot[row * XP + col]);
                B[nt][kt][1] = *reinterpret_cast<const uint32_t*>(&sm.wot[row * XP + col + 8]);
            }
        int cbase = nw * 16 + (lane & 3) * 2;
        float bo0[2], bo1[2];
#pragma unroll
        for (int nt = 0; nt < 2; nt++) {
            bo0[nt] = __ldg(&bo[cbase + nt * 8]);
            bo1[nt] = __ldg(&bo[cbase + nt * 8 + 1]);
        }
#pragma unroll 1
        for (int mt = 0; mt < 8; mt++) {
            int s0 = mw * 128 + mt * 16;
            uint32_t A[4][4];
#pragma unroll
            for (int kt = 0; kt < 4; kt++)
                ldmA(A[kt], s2u(&sm.vt[(s0 + (lane & 15)) * XP + kt * 16 + ((lane >> 4) << 3)]));
            float acc[2][4] = {{0, 0, 0, 0}, {0, 0, 0, 0}};
#pragma unroll
            for (int kt = 0; kt < 4; kt++)
#pragma unroll
                for (int nt = 0; nt < 2; nt++) mma16816(acc[nt], A[kt], B[nt][kt]);
            int r = s0 + (lane >> 2);
            float mkA = sm.maskS[r], mkB = sm.maskS[r + 8];
#pragma unroll
            for (int nt = 0; nt < 2; nt++) {
                *reinterpret_cast<float2*>(oBase + (size_t)r * rowStride + cbase + nt * 8) =
                    make_float2((acc[nt][0] + bo0[nt]) * mkA, (acc[nt][1] + bo1[nt]) * mkA);
                *reinterpret_cast<float2*>(oBase + (size_t)(r + 8) * rowStride + cbase + nt * 8) =
                    make_float2((acc[nt][2] + bo0[nt]) * mkB, (acc[nt][3] + bo1[nt]) * mkB);
            }
        }
    }
}

extern "C" void kernel_launch(void* const* d_in, const int* in_sizes, int n_in,
                              void* d_out, int out_size)
{
    (void)in_sizes; (void)n_in; (void)out_size;
    const float* m    = (const float*)d_in[0];
    const float* mask = (const float*)d_in[1];
    const float* lnw  = (const float*)d_in[2];
    const float* lnb  = (const float*)d_in[3];
    const float* wq   = (const float*)d_in[4];
    const float* wk   = (const float*)d_in[5];
    const float* wv   = (const float*)d_in[6];
    const float* wg   = (const float*)d_in[7];
    const float* bg   = (const float*)d_in[8];
    const float* wo   = (const float*)d_in[9];
    const float* bo   = (const float*)d_in[10];
    float* out = (float*)d_out;

    cudaFuncSetAttribute(msa_col_global_attn,
                         cudaFuncAttributeMaxDynamicSharedMemorySize,
                         (int)sizeof(SMem));
    msa_col_global_attn<<<Bb * Ll, NT, sizeof(SMem)>>>(
        m, mask, lnw, lnb, wq, wk, wv, wg, bg, wo, bo, out);
}

// round 11
// speedup vs baseline: 1.0177x; 1.0177x over previous
#include <cuda_runtime.h>
#include <cuda_fp16.h>
#include <cstdint>
#include <cstddef>

#define NT 512
#define XP 72   // halves per smem matrix row (144B: conflict-free ldmatrix, 16B-aligned)

namespace {
constexpr int Bb = 2, Ss = 512, Ll = 384, CMc = 64;

struct __align__(16) SMem {
    __half x[512 * XP];     // post-LN x fp16, row-major [s][c]      73,728B
    __half wvg[128 * XP];   // B rows n: n<64 -> wv col n, else wg col n-64; cols k
    __half wot[64 * XP];    // B rows n: wo col n
    float LG[8 * 512];      // logits -> attn [h][s]
    float maskS[512];
    float pbuf[16 * 64];    // LN qin partials; og partials (4 blocks x 64)
    __half a_h[8 * XP];     // a fp16 [h][j] (logits B tile)
    float qin[64];
    float qsm[64];
    float og[64];
    float bgS[64];
    float red[16];
};
}  // namespace

__device__ __forceinline__ uint32_t s2u(const void* p) {
    uint32_t a;
    asm("{ .reg .u64 t; cvta.to.shared.u64 t, %1; cvt.u32.u64 %0, t; }" : "=r"(a) : "l"(p));
    return a;
}
__device__ __forceinline__ void ldmA(uint32_t* a, uint32_t addr) {
    asm volatile("ldmatrix.sync.aligned.m8n8.x4.shared.b16 {%0,%1,%2,%3}, [%4];"
                 : "=r"(a[0]), "=r"(a[1]), "=r"(a[2]), "=r"(a[3]) : "r"(addr));
}
__device__ __forceinline__ void mma16816(float* d, const uint32_t* a, const uint32_t* b) {
    asm volatile(
        "mma.sync.aligned.m16n8k16.row.col.f32.f16.f16.f32 "
        "{%0,%1,%2,%3}, {%4,%5,%6,%7}, {%8,%9}, {%0,%1,%2,%3};"
        : "+f"(d[0]), "+f"(d[1]), "+f"(d[2]), "+f"(d[3])
        : "r"(a[0]), "r"(a[1]), "r"(a[2]), "r"(a[3]), "r"(b[0]), "r"(b[1]));
}
__device__ __forceinline__ float sgm(float x) { return 1.0f / (1.0f + __expf(-x)); }
__device__ __forceinline__ uint32_t packh2(float a, float b) {
    __half2 h = __floats2half2_rn(a, b);
    return *reinterpret_cast<uint32_t*>(&h);
}

__global__ void __launch_bounds__(NT, 1)
msa_col_global_attn(const float* __restrict__ m, const float* __restrict__ msa_mask,
                    const float* __restrict__ lnw, const float* __restrict__ lnb,
                    const float* __restrict__ wq, const float* __restrict__ wk,
                    const float* __restrict__ wv, const float* __restrict__ wg,
                    const float* __restrict__ bg, const float* __restrict__ wo,
                    const float* __restrict__ bo, float* __restrict__ out)
{
    extern __shared__ __align__(16) char smraw[];
    SMem& sm = *reinterpret_cast<SMem*>(smraw);
    const int tid = threadIdx.x;
    const int w = tid >> 5, lane = tid & 31;
    const int mw = w >> 2, nw = w & 3;
    const int b = blockIdx.x / Ll, l = blockIdx.x - b * Ll;
    const size_t rowStride = (size_t)Ll * CMc;
    const float* mBase = m + ((size_t)b * Ss * Ll + l) * CMc;
    float* oBase = out + ((size_t)b * Ss * Ll + l) * CMc;

    // ---- Phase 0: mask + weights + LayerNorm (round-9 form) + folded qin sum ----
    float mk = msa_mask[((size_t)b * Ss + tid) * Ll + l];
    sm.maskS[tid] = mk;
    {
        float ms = mk;
#pragma unroll
        for (int o = 16; o; o >>= 1) ms += __shfl_xor_sync(0xffffffffu, ms, o);
        if (lane == 0) sm.red[w] = ms;
    }
    for (int idx = tid; idx < 8192; idx += NT) {
        int n = idx & 127, k = idx >> 7;
        float v = (n < 64) ? __ldg(&wv[k * 64 + n]) : __ldg(&wg[k * 64 + (n - 64)]);
        sm.wvg[n * XP + k] = __float2half(v);
    }
    for (int idx = tid; idx < 4096; idx += NT) {
        int n = idx & 63, k = idx >> 6;
        sm.wot[n * XP + k] = __float2half(__ldg(&wo[k * 64 + n]));
    }
    if (tid < 64) sm.bgS[tid] = __ldg(&bg[tid]);
    {
        const float lwA = lnw[lane], lwB = lnw[lane + 32];
        const float lbA = lnb[lane], lbB = lnb[lane + 32];
        float qA = 0.f, qB = 0.f;
#pragma unroll 1
        for (int rb = 0; rb < 4; rb++) {
            float a0[8], a1[8];
#pragma unroll
            for (int r = 0; r < 8; r++) {
                int s = w * 32 + rb * 8 + r;
                const float* mp = mBase + (size_t)s * rowStride;
                a0[r] = mp[lane];
                a1[r] = mp[lane + 32];
            }
#pragma unroll
            for (int r = 0; r < 8; r++) {
                int s = w * 32 + rb * 8 + r;
                float su = a0[r] + a1[r];
                float sq = fmaf(a0[r], a0[r], a1[r] * a1[r]);
#pragma unroll
                for (int o = 16; o; o >>= 1) {
                    su += __shfl_xor_sync(0xffffffffu, su, o);
                    sq += __shfl_xor_sync(0xffffffffu, sq, o);
                }
                float mu = su * (1.0f / 64.0f);
                float var = sq * (1.0f / 64.0f) - mu * mu;
                float rs = rsqrtf(var + 1e-5f);
                float vA = (a0[r] - mu) * rs * lwA + lbA;
                float vB = (a1[r] - mu) * rs * lwB + lbB;
                sm.x[s * XP + lane]      = __float2half(vA);
                sm.x[s * XP + lane + 32] = __float2half(vB);
                float mks = __shfl_sync(0xffffffffu, mk, rb * 8 + r);
                qA = fmaf(vA, mks, qA);
                qB = fmaf(vB, mks, qB);
            }
        }
        sm.pbuf[w * 64 + lane]      = qA;
        sm.pbuf[w * 64 + lane + 32] = qB;
    }
    __syncthreads();  // S1

    // ---- warp-0 chain: qin -> q -> a_h (fp16, [h][j]) ----
    if (w == 0) {
        float d = 0.f;
#pragma unroll
        for (int i = 0; i < 16; i++) d += sm.red[i];
        float inv = 1.0f / fmaxf(d, 1.0f);
        float q0 = 0.f, q1 = 0.f;
#pragma unroll
        for (int i = 0; i < 16; i++) {
            q0 += sm.pbuf[i * 64 + lane];
            q1 += sm.pbuf[i * 64 + lane + 32];
        }
        sm.qin[lane] = q0 * inv;
        sm.qin[lane + 32] = q1 * inv;
        __syncwarp();
        float a0 = 0.f, a1 = 0.f;
#pragma unroll
        for (int j = 0; j < 64; j++) {
            float qj = sm.qin[j];
            a0 = fmaf(qj, __ldg(&wq[j * 64 + lane]), a0);
            a1 = fmaf(qj, __ldg(&wq[j * 64 + lane + 32]), a1);
        }
        sm.qsm[lane] = a0;
        sm.qsm[lane + 32] = a1;
        __syncwarp();
#pragma unroll 1
        for (int t = 0; t < 16; t++) {
            int idx = t * 32 + lane;
            int j = idx >> 3, h = idx & 7;
            float acc = 0.f;
#pragma unroll
            for (int c = 0; c < 8; c++)
                acc = fmaf(sm.qsm[h * 8 + c], __ldg(&wk[j * 64 + h * 8 + c]), acc);
            sm.a_h[h * XP + j] = __float2half(acc * 0.35355339059327373f);  // 1/sqrt(C)
        }
    }
    __syncthreads();  // S2

    // ---- Logits via HMMA: logits[s,h] = x[s,:] @ a[:,h], masked -> LG fp32 ----
    {
        uint32_t Bf[4][2];
#pragma unroll
        for (int kt = 0; kt < 4; kt++) {
            int row = lane >> 2;
            int col = kt * 16 + (lane & 3) * 2;
            Bf[kt][0] = *reinterpret_cast<const uint32_t*>(&sm.a_h[row * XP + col]);
            Bf[kt][1] = *reinterpret_cast<const uint32_t*>(&sm.a_h[row * XP + col + 8]);
        }
#pragma unroll
        for (int mt = 0; mt < 2; mt++) {
            int s0 = w * 32 + mt * 16;
            uint32_t A[4][4];
#pragma unroll
            for (int kt = 0; kt < 4; kt++)
                ldmA(A[kt], s2u(&sm.x[(s0 + (lane & 15)) * XP + kt * 16 + ((lane >> 4) << 3)]));
            float acc[4] = {0, 0, 0, 0};
#pragma unroll
            for (int kt = 0; kt < 4; kt++) mma16816(acc, A[kt], Bf[kt]);
            int r = s0 + (lane >> 2);
            int h0 = (lane & 3) * 2;
            float mkA = sm.maskS[r], mkB = sm.maskS[r + 8];
            sm.LG[h0 * 512 + r]           = (mkA != 0.0f) ? acc[0] : -1e9f;
            sm.LG[(h0 + 1) * 512 + r]     = (mkA != 0.0f) ? acc[1] : -1e9f;
            sm.LG[h0 * 512 + r + 8]       = (mkB != 0.0f) ? acc[2] : -1e9f;
            sm.LG[(h0 + 1) * 512 + r + 8] = (mkB != 0.0f) ? acc[3] : -1e9f;
        }
    }
    __syncthreads();  // S3

    // ---- softmax, warp w<8 owns head w ----
    if (w < 8) {
        float vals[16];
        float lm = -3.4e38f;
#pragma unroll
        for (int k = 0; k < 16; k++) {
            vals[k] = sm.LG[w * 512 + lane + k * 32];
            lm = fmaxf(lm, vals[k]);
        }
#pragma unroll
        for (int o = 16; o; o >>= 1) lm = fmaxf(lm, __shfl_xor_sync(0xffffffffu, lm, o));
        float ls = 0.f;
#pragma unroll
        for (int k = 0; k < 16; k++) {
            vals[k] = __expf(vals[k] - lm);
            ls += vals[k];
        }
#pragma unroll
        for (int o = 16; o; o >>= 1) ls += __shfl_xor_sync(0xffffffffu, ls, o);
        float inv = 1.0f / ls;
#pragma unroll
        for (int k = 0; k < 16; k++) sm.LG[w * 512 + lane + k * 32] = vals[k] * inv;
    }
    __syncthreads();  // S4: attn ready

    // ---- Fused Pass V + og: og[c] += attn[h(c)][r] * (x@wv)[r][c], all in regs ----
    {
        uint32_t B[2][4][2];
#pragma unroll
        for (int nt = 0; nt < 2; nt++)
#pragma unroll
            for (int kt = 0; kt < 4; kt++) {
                int row = nw * 16 + nt * 8 + (lane >> 2);
                int col = kt * 16 + (lane & 3) * 2;
                B[nt][kt][0] = *reinterpret_cast<const uint32_t*>(&sm.wvg[row * XP + col]);
                B[nt][kt][1] = *reinterpret_cast<const uint32_t*>(&sm.wvg[row * XP + col + 8]);
            }
        float ogp[4] = {0, 0, 0, 0};
        const int h0 = 2 * nw, h1 = 2 * nw + 1;
#pragma unroll 1
        for (int mt = 0; mt < 8; mt++) {
            int s0 = mw * 128 + mt * 16;
            uint32_t A[4][4];
#pragma unroll
            for (int kt = 0; kt < 4; kt++)
                ldmA(A[kt], s2u(&sm.x[(s0 + (lane & 15)) * XP + kt * 16 + ((lane >> 4) << 3)]));
            float acc[2][4] = {{0, 0, 0, 0}, {0, 0, 0, 0}};
#pragma unroll
            for (int kt = 0; kt < 4; kt++)
#pragma unroll
                for (int nt = 0; nt < 2; nt++) mma16816(acc[nt], A[kt], B[nt][kt]);
            int r = s0 + (lane >> 2);
            float aA0 = sm.LG[h0 * 512 + r], aB0 = sm.LG[h0 * 512 + r + 8];
            float aA1 = sm.LG[h1 * 512 + r], aB1 = sm.LG[h1 * 512 + r + 8];
            ogp[0] = fmaf(aA0, acc[0][0], fmaf(aB0, acc[0][2], ogp[0]));
            ogp[1] = fmaf(aA0, acc[0][1], fmaf(aB0, acc[0][3], ogp[1]));
            ogp[2] = fmaf(aA1, acc[1][0], fmaf(aB1, acc[1][2], ogp[2]));
            ogp[3] = fmaf(aA1, acc[1][1], fmaf(aB1, acc[1][3], ogp[3]));
        }
#pragma unroll
        for (int k = 0; k < 4; k++) {
            ogp[k] += __shfl_xor_sync(0xffffffffu, ogp[k], 4);
            ogp[k] += __shfl_xor_sync(0xffffffffu, ogp[k], 8);
            ogp[k] += __shfl_xor_sync(0xffffffffu, ogp[k], 16);
        }
        if (lane < 4) {
            int c0 = nw * 16 + lane * 2;
            sm.pbuf[mw * 64 + c0]     = ogp[0];
            sm.pbuf[mw * 64 + c0 + 1] = ogp[1];
            sm.pbuf[mw * 64 + c0 + 8] = ogp[2];
            sm.pbuf[mw * 64 + c0 + 9] = ogp[3];
        }
    }
    __syncthreads();  // S5
    if (tid < 64)
        sm.og[tid] = sm.pbuf[tid] + sm.pbuf[64 + tid] + sm.pbuf[128 + tid] + sm.pbuf[192 + tid];
    __syncthreads();  // S6: og ready

    // ---- Fused Pass G+O: per warp rows w*32..+31 ----
    {
        const int k0 = (lane & 3) * 2;
#pragma unroll 1
        for (int mt2 = 0; mt2 < 2; mt2++) {
            int s0 = w * 32 + mt2 * 16;
            uint32_t Ax[4][4];
#pragma unroll
            for (int kt = 0; kt < 4; kt++)
                ldmA(Ax[kt], s2u(&sm.x[(s0 + (lane & 15)) * XP + kt * 16 + ((lane >> 4) << 3)]));
            // GEMM1: gpre = x @ wg (all 64 cols)
            float gacc[8][4];
#pragma unroll
            for (int nt = 0; nt < 8; nt++)
#pragma unroll
                for (int q = 0; q < 4; q++) gacc[nt][q] = 0.f;
#pragma unroll
            for (int nt = 0; nt < 8; nt++) {
                uint32_t Bg[4][2];
#pragma unroll
                for (int kt = 0; kt < 4; kt++) {
                    int row = 64 + nt * 8 + (lane >> 2);
                    int col = kt * 16 + k0;
                    Bg[kt][0] = *reinterpret_cast<const uint32_t*>(&sm.wvg[row * XP + col]);
                    Bg[kt][1] = *reinterpret_cast<const uint32_t*>(&sm.wvg[row * XP + col + 8]);
                }
#pragma unroll
                for (int kt = 0; kt < 4; kt++) mma16816(gacc[nt], Ax[kt], Bg[kt]);
            }
            // epilogue 1: t = og * sigmoid(gpre + bg); repack D-frags -> A-frags (fp16)
            uint32_t Ap[4][4];
#pragma unroll
            for (int nt = 0; nt < 8; nt++) {
                int c = nt * 8 + k0;
                float ogv0 = sm.og[c], ogv1 = sm.og[c + 1];
                float bg0 = sm.bgS[c], bg1 = sm.bgS[c + 1];
                float t0 = ogv0 * sgm(gacc[nt][0] + bg0);
                float t1 = ogv1 * sgm(gacc[nt][1] + bg1);
                float t2 = ogv0 * sgm(gacc[nt][2] + bg0);
                float t3 = ogv1 * sgm(gacc[nt][3] + bg1);
                int kt2 = nt >> 1, hi = nt & 1;
                Ap[kt2][hi * 2]     = packh2(t0, t1);
                Ap[kt2][hi * 2 + 1] = packh2(t2, t3);
            }
            // GEMM2: out = t @ wo + bo, masked, direct global store
            int r = s0 + (lane >> 2);
            float mkA = sm.maskS[r], mkB = sm.maskS[r + 8];
#pragma unroll
            for (int nt2 = 0; nt2 < 8; nt2++) {
                uint32_t Bo[4][2];
#pragma unroll
                for (int kt = 0; kt < 4; kt++) {
                    int row = nt2 * 8 + (lane >> 2);
                    int col = kt * 16 + k0;
                    Bo[kt][0] = *reinterpret_cast<const uint32_t*>(&sm.wot[row * XP + col]);
                    Bo[kt][1] = *reinterpret_cast<const uint32_t*>(&sm.wot[row * XP + col + 8]);
                }
                float acc2[4] = {0, 0, 0, 0};
#pragma unroll
                for (int kt = 0; kt < 4; kt++) mma16816(acc2, Ap[kt], Bo[kt]);
                int c = nt2 * 8 + k0;
                float bo0 = __ldg(&bo[c]), bo1 = __ldg(&bo[c + 1]);
                *reinterpret_cast<float2*>(oBase + (size_t)r * rowStride + c) =
                    make_float2((acc2[0] + bo0) * mkA, (acc2[1] + bo1) * mkA);
                *reinterpret_cast<float2*>(oBase + (size_t)(r + 8) * rowStride + c) =
                    make_float2((acc2[2] + bo0) * mkB, (acc2[3] + bo1) * mkB);
            }
        }
    }
}

extern "C" void kernel_launch(void* const* d_in, const int* in_sizes, int n_in,
                              void* d_out, int out_size)
{
    (void)in_sizes; (void)n_in; (void)out_size;
    const float* m    = (const float*)d_in[0];
    const float* mask = (const float*)d_in[1];
    const float* lnw  = (const float*)d_in[2];
    const float* lnb  = (const float*)d_in[3];
    const float* wq   = (const float*)d_in[4];
    const float* wk   = (const float*)d_in[5];
    const float* wv   = (const float*)d_in[6];
    const float* wg   = (const float*)d_in[7];
    const float* bg   = (const float*)d_in[8];
    const float* wo   = (const float*)d_in[9];
    const float* bo   = (const float*)d_in[10];
    float* out = (float*)d_out;

    cudaFuncSetAttribute(msa_col_global_attn,
                         cudaFuncAttributeMaxDynamicSharedMemorySize,
                         (int)sizeof(SMem));
    msa_col_global_attn<<<Bb * Ll, NT, sizeof(SMem)>>>(
        m, mask, lnw, lnb, wq, wk, wv, wg, bg, wo, bo, out);
}

// round 13
// speedup vs baseline: 1.2321x; 1.2107x over previous
#include <cuda_runtime.h>
#include <cuda_fp16.h>
#include <cstdint>
#include <cstddef>

#define NT 256
#define XP 72   // halves per smem matrix row (144B: conflict-free ldmatrix, 16B-aligned)

namespace {
constexpr int Bb = 2, Ss = 512, Ll = 384, CMc = 64;

struct __align__(16) SMem {
    __half x[512 * XP];      // post-LN x fp16, row-major [s][c]     73,728B
    __half wvB[64 * XP];     // wv^T tile: row n, col k               9,216B
    union {
        float LG[8 * 512];   // logits->attn [h][s]                  16,384B
        struct { __half wgB[64 * XP]; __half woB[64 * XP]; } go;  // 18,432B
    } u;
    float maskS[512];
    float pbuf[8 * 64];      // qin partials; og partials
    __half a_h[8 * XP];      // a fp16 [h][j]
    float qin[64];
    float qsm[64];
    float og[64];
    float bgS[64];
    float red[8];
};
}  // namespace

__device__ __forceinline__ uint32_t s2u(const void* p) {
    uint32_t a;
    asm("{ .reg .u64 t; cvta.to.shared.u64 t, %1; cvt.u32.u64 %0, t; }" : "=r"(a) : "l"(p));
    return a;
}
__device__ __forceinline__ void ldmA(uint32_t* a, uint32_t addr) {
    asm volatile("ldmatrix.sync.aligned.m8n8.x4.shared.b16 {%0,%1,%2,%3}, [%4];"
                 : "=r"(a[0]), "=r"(a[1]), "=r"(a[2]), "=r"(a[3]) : "r"(addr));
}
__device__ __forceinline__ void mma16816(float* d, const uint32_t* a, const uint32_t* b) {
    asm volatile(
        "mma.sync.aligned.m16n8k16.row.col.f32.f16.f16.f32 "
        "{%0,%1,%2,%3}, {%4,%5,%6,%7}, {%8,%9}, {%0,%1,%2,%3};"
        : "+f"(d[0]), "+f"(d[1]), "+f"(d[2]), "+f"(d[3])
        : "r"(a[0]), "r"(a[1]), "r"(a[2]), "r"(a[3]), "r"(b[0]), "r"(b[1]));
}
__device__ __forceinline__ float sgm(float x) { return 1.0f / (1.0f + __expf(-x)); }
__device__ __forceinline__ uint32_t packh2(float a, float b) {
    __half2 h = __floats2half2_rn(a, b);
    return *reinterpret_cast<uint32_t*>(&h);
}

__global__ void __launch_bounds__(NT, 2)
msa_col_global_attn(const float* __restrict__ m, const float* __restrict__ msa_mask,
                    const float* __restrict__ lnw, const float* __restrict__ lnb,
                    const float* __restrict__ wq, const float* __restrict__ wk,
                    const float* __restrict__ wv, const float* __restrict__ wg,
                    const float* __restrict__ bg, const float* __restrict__ wo,
                    const float* __restrict__ bo, float* __restrict__ out)
{
    extern __shared__ __align__(16) char smraw[];
    SMem& sm = *reinterpret_cast<SMem*>(smraw);
    const int tid = threadIdx.x;
    const int w = tid >> 5, lane = tid & 31;
    const int b = blockIdx.x / Ll, l = blockIdx.x - b * Ll;
    const size_t rowStride = (size_t)Ll * CMc;
    const float* mBase = m + ((size_t)b * Ss * Ll + l) * CMc;
    float* oBase = out + ((size_t)b * Ss * Ll + l) * CMc;

    // ---- Phase 0: mask, wv tile, bg, LayerNorm (warp owns 64 rows) + qin fold ----
    const int row0 = w * 64 + lane, row1 = row0 + 32;
    float mkA = msa_mask[((size_t)b * Ss + row0) * Ll + l];
    float mkB = msa_mask[((size_t)b * Ss + row1) * Ll + l];
    sm.maskS[row0] = mkA;
    sm.maskS[row1] = mkB;
    {
        float ms = mkA + mkB;
#pragma unroll
        for (int o = 16; o; o >>= 1) ms += __shfl_xor_sync(0xffffffffu, ms, o);
        if (lane == 0) sm.red[w] = ms;
    }
    for (int idx = tid; idx < 4096; idx += NT) {
        int n = idx & 63, k = idx >> 6;
        sm.wvB[n * XP + k] = __float2half(__ldg(&wv[k * 64 + n]));
    }
    if (tid < 64) sm.bgS[tid] = __ldg(&bg[tid]);
    {
        const float lwA = lnw[lane], lwB = lnw[lane + 32];
        const float lbA = lnb[lane], lbB = lnb[lane + 32];
        float qA = 0.f, qB = 0.f;
#pragma unroll 1
        for (int rb = 0; rb < 8; rb++) {
            float a0[8], a1[8];
#pragma unroll
            for (int r = 0; r < 8; r++) {
                int s = w * 64 + rb * 8 + r;
                const float* mp = mBase + (size_t)s * rowStride;
                a0[r] = mp[lane];
                a1[r] = mp[lane + 32];
            }
            float msel = (rb < 4) ? mkA : mkB;
            int bidx = (rb < 4) ? rb * 8 : rb * 8 - 32;
#pragma unroll
            for (int r = 0; r < 8; r++) {
                int s = w * 64 + rb * 8 + r;
                float su = a0[r] + a1[r];
                float sq = fmaf(a0[r], a0[r], a1[r] * a1[r]);
#pragma unroll
                for (int o = 16; o; o >>= 1) {
                    su += __shfl_xor_sync(0xffffffffu, su, o);
                    sq += __shfl_xor_sync(0xffffffffu, sq, o);
                }
                float mu = su * (1.0f / 64.0f);
                float var = sq * (1.0f / 64.0f) - mu * mu;
                float rs = rsqrtf(var + 1e-5f);
                float vA = (a0[r] - mu) * rs * lwA + lbA;
                float vB = (a1[r] - mu) * rs * lwB + lbB;
                sm.x[s * XP + lane]      = __float2half(vA);
                sm.x[s * XP + lane + 32] = __float2half(vB);
                float mks = __shfl_sync(0xffffffffu, msel, bidx + r);
                qA = fmaf(vA, mks, qA);
                qB = fmaf(vB, mks, qB);
            }
        }
        sm.pbuf[w * 64 + lane]      = qA;
        sm.pbuf[w * 64 + lane + 32] = qB;
    }
    __syncthreads();  // S1

    // ---- warp-0 chain: qin -> q -> a_h (fp16 [h][j]) ----
    if (w == 0) {
        float d = 0.f;
#pragma unroll
        for (int i = 0; i < 8; i++) d += sm.red[i];
        float inv = 1.0f / fmaxf(d, 1.0f);
        float q0 = 0.f, q1 = 0.f;
#pragma unroll
        for (int i = 0; i < 8; i++) {
            q0 += sm.pbuf[i * 64 + lane];
            q1 += sm.pbuf[i * 64 + lane + 32];
        }
        sm.qin[lane] = q0 * inv;
        sm.qin[lane + 32] = q1 * inv;
        __syncwarp();
        float a0 = 0.f, a1 = 0.f;
#pragma unroll
        for (int j = 0; j < 64; j++) {
            float qj = sm.qin[j];
            a0 = fmaf(qj, __ldg(&wq[j * 64 + lane]), a0);
            a1 = fmaf(qj, __ldg(&wq[j * 64 + lane + 32]), a1);
        }
        sm.qsm[lane] = a0;
        sm.qsm[lane + 32] = a1;
        __syncwarp();
#pragma unroll 1
        for (int t = 0; t < 16; t++) {
            int idx = t * 32 + lane;
            int j = idx >> 3, h = idx & 7;
            float acc = 0.f;
#pragma unroll
            for (int c = 0; c < 8; c++)
                acc = fmaf(sm.qsm[h * 8 + c], __ldg(&wk[j * 64 + h * 8 + c]), acc);
            sm.a_h[h * XP + j] = __float2half(acc * 0.35355339059327373f);  // 1/sqrt(C)
        }
    }
    __syncthreads();  // S2

    // ---- Logits via HMMA: warp w rows w*64..+63 ----
    {
        uint32_t Bf[4][2];
#pragma unroll
        for (int kt = 0; kt < 4; kt++) {
            int row = lane >> 2;
            int col = kt * 16 + (lane & 3) * 2;
            Bf[kt][0] = *reinterpret_cast<const uint32_t*>(&sm.a_h[row * XP + col]);
            Bf[kt][1] = *reinterpret_cast<const uint32_t*>(&sm.a_h[row * XP + col + 8]);
        }
#pragma unroll
        for (int mt = 0; mt < 4; mt++) {
            int s0 = w * 64 + mt * 16;
            uint32_t A[4][4];
#pragma unroll
            for (int kt = 0; kt < 4; kt++)
                ldmA(A[kt], s2u(&sm.x[(s0 + (lane & 15)) * XP + kt * 16 + ((lane >> 4) << 3)]));
            float acc[4] = {0, 0, 0, 0};
#pragma unroll
            for (int kt = 0; kt < 4; kt++) mma16816(acc, A[kt], Bf[kt]);
            int r = s0 + (lane >> 2);
            int h0 = (lane & 3) * 2;
            float mA = sm.maskS[r], mB = sm.maskS[r + 8];
            sm.u.LG[h0 * 512 + r]           = (mA != 0.0f) ? acc[0] : -1e9f;
            sm.u.LG[(h0 + 1) * 512 + r]     = (mA != 0.0f) ? acc[1] : -1e9f;
            sm.u.LG[h0 * 512 + r + 8]       = (mB != 0.0f) ? acc[2] : -1e9f;
            sm.u.LG[(h0 + 1) * 512 + r + 8] = (mB != 0.0f) ? acc[3] : -1e9f;
        }
    }
    __syncthreads();  // S3

    // ---- softmax, warp w owns head w ----
    {
        float vals[16];
        float lm = -3.4e38f;
#pragma unroll
        for (int k = 0; k < 16; k++) {
            vals[k] = sm.u.LG[w * 512 + lane + k * 32];
            lm = fmaxf(lm, vals[k]);
        }
#pragma unroll
        for (int o = 16; o; o >>= 1) lm = fmaxf(lm, __shfl_xor_sync(0xffffffffu, lm, o));
        float ls = 0.f;
#pragma unroll
        for (int k = 0; k < 16; k++) {
            vals[k] = __expf(vals[k] - lm);
            ls += vals[k];
        }
#pragma unroll
        for (int o = 16; o; o >>= 1) ls += __shfl_xor_sync(0xffffffffu, ls, o);
        float inv = 1.0f / ls;
#pragma unroll
        for (int k = 0; k < 16; k++) sm.u.LG[w * 512 + lane + k * 32] = vals[k] * inv;
    }
    __syncthreads();  // S4: attn ready

    // ---- Fused Pass V + og: warp w rows w*64..+63, all 64 cols ----
    {
        float ogp[16];
#pragma unroll
        for (int k = 0; k < 16; k++) ogp[k] = 0.f;
        const int k0 = (lane & 3) * 2;
#pragma unroll 1
        for (int mt = 0; mt < 4; mt++) {
            int s0 = w * 64 + mt * 16;
            uint32_t A[4][4];
#pragma unroll
            for (int kt = 0; kt < 4; kt++)
                ldmA(A[kt], s2u(&sm.x[(s0 + (lane & 15)) * XP + kt * 16 + ((lane >> 4) << 3)]));
            int r = s0 + (lane >> 2);
#pragma unroll
            for (int nt = 0; nt < 8; nt++) {
                uint32_t Bv[4][2];
#pragma unroll
                for (int kt = 0; kt < 4; kt++) {
                    int row = nt * 8 + (lane >> 2);
                    int col = kt * 16 + k0;
                    Bv[kt][0] = *reinterpret_cast<const uint32_t*>(&sm.wvB[row * XP + col]);
                    Bv[kt][1] = *reinterpret_cast<const uint32_t*>(&sm.wvB[row * XP + col + 8]);
                }
                float acc[4] = {0, 0, 0, 0};
#pragma unroll
                for (int kt = 0; kt < 4; kt++) mma16816(acc, A[kt], Bv[kt]);
                float aA = sm.u.LG[nt * 512 + r];
                float aB = sm.u.LG[nt * 512 + r + 8];
                ogp[2 * nt]     = fmaf(aA, acc[0], fmaf(aB, acc[2], ogp[2 * nt]));
                ogp[2 * nt + 1] = fmaf(aA, acc[1], fmaf(aB, acc[3], ogp[2 * nt + 1]));
            }
        }
#pragma unroll
        for (int k = 0; k < 16; k++) {
            ogp[k] += __shfl_xor_sync(0xffffffffu, ogp[k], 4);
            ogp[k] += __shfl_xor_sync(0xffffffffu, ogp[k], 8);
            ogp[k] += __shfl_xor_sync(0xffffffffu, ogp[k], 16);
        }
        if (lane < 4) {
#pragma unroll
            for (int nt = 0; nt < 8; nt++) {
                sm.pbuf[w * 64 + nt * 8 + k0]     = ogp[2 * nt];
                sm.pbuf[w * 64 + nt * 8 + k0 + 1] = ogp[2 * nt + 1];
            }
        }
    }
    __syncthreads();  // S5: LG dead from here; og partials ready

    // ---- og reduce + stage wg/wo tiles into the union ----
    if (tid < 64) {
        float acc = 0.f;
#pragma unroll
        for (int w2 = 0; w2 < 8; w2++) acc += sm.pbuf[w2 * 64 + tid];
        sm.og[tid] = acc;
    }
    for (int idx = tid; idx < 4096; idx += NT) {
        int n = idx & 63, k = idx >> 6;
        sm.u.go.wgB[n * XP + k] = __float2half(__ldg(&wg[k * 64 + n]));
        sm.u.go.woB[n * XP + k] = __float2half(__ldg(&wo[k * 64 + n]));
    }
    __syncthreads();  // S6: og + wg/wo tiles ready

    // ---- Fused G+O: warp w rows w*64..+63 ----
    {
        const int k0 = (lane & 3) * 2;
#pragma unroll 1
        for (int mt2 = 0; mt2 < 4; mt2++) {
            int s0 = w * 64 + mt2 * 16;
            uint32_t Ax[4][4];
#pragma unroll
            for (int kt = 0; kt < 4; kt++)
                ldmA(Ax[kt], s2u(&sm.x[(s0 + (lane & 15)) * XP + kt * 16 + ((lane >> 4) << 3)]));
            // GEMM1: gpre = x @ wg
            float gacc[8][4];
#pragma unroll
            for (int nt = 0; nt < 8; nt++)
#pragma unroll
                for (int q = 0; q < 4; q++) gacc[nt][q] = 0.f;
#pragma unroll
            for (int nt = 0; nt < 8; nt++) {
                uint32_t Bg[4][2];
#pragma unroll
                for (int kt = 0; kt < 4; kt++) {
                    int row = nt * 8 + (lane >> 2);
                    int col = kt * 16 + k0;
                    Bg[kt][0] = *reinterpret_cast<const uint32_t*>(&sm.u.go.wgB[row * XP + col]);
                    Bg[kt][1] = *reinterpret_cast<const uint32_t*>(&sm.u.go.wgB[row * XP + col + 8]);
                }
#pragma unroll
                for (int kt = 0; kt < 4; kt++) mma16816(gacc[nt], Ax[kt], Bg[kt]);
            }
            // epilogue: t = og * sigmoid(gpre + bg); repack D-frags -> A-frags
            uint32_t Ap[4][4];
#pragma unroll
            for (int nt = 0; nt < 8; nt++) {
                int c = nt * 8 + k0;
                float ogv0 = sm.og[c], ogv1 = sm.og[c + 1];
                float bg0 = sm.bgS[c], bg1 = sm.bgS[c + 1];
                float t0 = ogv0 * sgm(gacc[nt][0] + bg0);
                float t1 = ogv1 * sgm(gacc[nt][1] + bg1);
                float t2 = ogv0 * sgm(gacc[nt][2] + bg0);
                float t3 = ogv1 * sgm(gacc[nt][3] + bg1);
                int kt2 = nt >> 1, hi = nt & 1;
                Ap[kt2][hi * 2]     = packh2(t0, t1);
                Ap[kt2][hi * 2 + 1] = packh2(t2, t3);
            }
            // GEMM2: out = (t @ wo + bo) * mask -> global
            int r = s0 + (lane >> 2);
            float mA = sm.maskS[r], mB = sm.maskS[r + 8];
#pragma unroll
            for (int nt2 = 0; nt2 < 8; nt2++) {
                uint32_t Bo[4][2];
#pragma unroll
                for (int kt = 0; kt < 4; kt++) {
                    int row = nt2 * 8 + (lane >> 2);
                    int col = kt * 16 + k0;
                    Bo[kt][0] = *reinterpret_cast<const uint32_t*>(&sm.u.go.woB[row * XP + col]);
                    Bo[kt][1] = *reinterpret_cast<const uint32_t*>(&sm.u.go.woB[row * XP + col + 8]);
                }
                float acc2[4] = {0, 0, 0, 0};
#pragma unroll
                for (int kt = 0; kt < 4; kt++) mma16816(acc2, Ap[kt], Bo[kt]);
                int c = nt2 * 8 + k0;
                float bo0 = __ldg(&bo[c]), bo1 = __ldg(&bo[c + 1]);
                *reinterpret_cast<float2*>(oBase + (size_t)r * rowStride + c) =
                    make_float2((acc2[0] + bo0) * mA, (acc2[1] + bo1) * mA);
                *reinterpret_cast<float2*>(oBase + (size_t)(r + 8) * rowStride + c) =
                    make_float2((acc2[2] + bo0) * mB, (acc2[3] + bo1) * mB);
            }
        }
    }
}

extern "C" void kernel_launch(void* const* d_in, const int* in_sizes, int n_in,
                              void* d_out, int out_size)
{
    (void)in_sizes; (void)n_in; (void)out_size;
    const float* m    = (const float*)d_in[0];
    const float* mask = (const float*)d_in[1];
    const float* lnw  = (const float*)d_in[2];
    const float* lnb  = (const float*)d_in[3];
    const float* wq   = (const float*)d_in[4];
    const float* wk   = (const float*)d_in[5];
    const float* wv   = (const float*)d_in[6];
    const float* wg   = (const float*)d_in[7];
    const float* bg   = (const float*)d_in[8];
    const float* wo   = (const float*)d_in[9];
    const float* bo   = (const float*)d_in[10];
    float* out = (float*)d_out;

    cudaFuncSetAttribute(msa_col_global_attn,
                         cudaFuncAttributeMaxDynamicSharedMemorySize,
                         (int)sizeof(SMem));
    msa_col_global_attn<<<Bb * Ll, NT, sizeof(SMem)>>>(
        m, mask, lnw, lnb, wq, wk, wv, wg, bg, wo, bo, out);
}